// round 9
// baseline (speedup 1.0000x reference)
#include <cuda_runtime.h>
#include <cuda_bf16.h>
#include <cstdint>

#define TPB        256
#define CHUNK_F4   512                     // float4s per chunk = 8 KB
#define CHUNK_B    (CHUNK_F4 * 16)         // bytes per chunk
#define EPS        6.0e-5f                 // edge window in u-units

// out[i] = bins[ clip(searchsorted_right(bins, max(logit(x), bins[0])) - 1, 0, 63) ]
// bins = linspace(-6,6,64) uniform. Fast path (MUFU.LG2) + exact rare fixup.

__device__ __forceinline__ float lg2a(float v) {
    float r;
    asm("lg2.approx.ftz.f32 %0, %1;" : "=f"(r) : "f"(v));
    return r;
}

__device__ __forceinline__ float slow_val(float x, const float* __restrict__ bins) {
    float s    = logf(x) - logf(1.0f - x);      // accurate; rare path only
    float sbar = fmaxf(s, __ldg(bins));
    float uu   = (sbar + 6.0f) * (63.0f / 12.0f);
    int i = (int)floorf(uu);
    i = i < 0 ? 0 : (i > 63 ? 63 : i);
    if (sbar < __ldg(bins + i))                      i -= 1;
    else if (i < 63 && sbar >= __ldg(bins + i + 1))  i += 1;
    return __ldg(bins + i);
}

#define KU   (0.6931471805599453f * 5.25f)   /* ln2 * 63/12 */
#define STEP (12.0f / 63.0f)

#define ELEM(XV, VOUT, ACC) do {                                      \
    float _t  = lg2a(XV) - lg2a(1.0f - (XV));                         \
    float _h  = fmaf(_t, KU, 31.0f);                                  \
    float _fu = rintf(_h);                                            \
    float _d  = _h - _fu;                                             \
    ACC = fmaxf(ACC, fabsf(_d));                                      \
    VOUT = fminf(fmaxf(fmaf(_fu, STEP, -6.0f), -6.0f), 6.0f);         \
} while (0)

#define FIX(XV, VOUT) do {                                            \
    float _h = fmaf(lg2a(XV) - lg2a(1.0f - (XV)), KU, 31.0f);         \
    float _d = _h - rintf(_h);                                        \
    if (fabsf(_d) >= 0.5f - EPS) VOUT = slow_val(XV, bins);           \
} while (0)

__device__ __forceinline__ void mbar_wait_acq(uint32_t mb, uint32_t phase) {
    uint32_t done = 0;
    while (!done) {
        asm volatile(
            "{\n\t.reg .pred p;\n\t"
            "mbarrier.try_wait.parity.acquire.cta.shared::cta.b64 p, [%1], %2, 0x989680;\n\t"
            "selp.b32 %0, 1, 0, p;\n\t}"
            : "=r"(done) : "r"(mb), "r"(phase) : "memory");
    }
}

// Exact-fit pipelined kernel: block b owns float4s [b*1024, (b+1)*1024),
// split into 2 chunks of 512 float4s staged via cp.async.bulk.
__global__ __launch_bounds__(TPB)
void logodds_tma_kernel(const float* __restrict__ Xs,
                        const float* __restrict__ bins,
                        float* __restrict__ out) {
    __shared__ alignas(16) float4 buf[2][CHUNK_F4];
    __shared__ alignas(8)  uint64_t mbar_s[2];

    int tid = threadIdx.x;
    uint32_t mb0 = (uint32_t)__cvta_generic_to_shared(&mbar_s[0]);
    uint32_t mb1 = (uint32_t)__cvta_generic_to_shared(&mbar_s[1]);

    if (tid == 0) {
        asm volatile("mbarrier.init.shared.b64 [%0], 1;" :: "r"(mb0) : "memory");
        asm volatile("mbarrier.init.shared.b64 [%0], 1;" :: "r"(mb1) : "memory");
        asm volatile("fence.proxy.async.shared::cta;" ::: "memory");
    }
    __syncthreads();

    long base0 = (long)blockIdx.x * (2 * CHUNK_F4);   // float4 index
    long base1 = base0 + CHUNK_F4;

    // Issue BOTH bulk copies up front (thread 0); warps never touch LDG.
    if (tid == 0) {
        uint32_t d0 = (uint32_t)__cvta_generic_to_shared(&buf[0][0]);
        uint32_t d1 = (uint32_t)__cvta_generic_to_shared(&buf[1][0]);
        const char* s0 = (const char*)Xs + base0 * 16;
        const char* s1 = (const char*)Xs + base1 * 16;
        asm volatile("mbarrier.arrive.expect_tx.shared.b64 _, [%0], %1;"
                     :: "r"(mb0), "r"((uint32_t)CHUNK_B) : "memory");
        asm volatile("cp.async.bulk.shared::cta.global.mbarrier::complete_tx::bytes "
                     "[%0], [%1], %2, [%3];"
                     :: "r"(d0), "l"(s0), "r"((uint32_t)CHUNK_B), "r"(mb0) : "memory");
        asm volatile("mbarrier.arrive.expect_tx.shared.b64 _, [%0], %1;"
                     :: "r"(mb1), "r"((uint32_t)CHUNK_B) : "memory");
        asm volatile("cp.async.bulk.shared::cta.global.mbarrier::complete_tx::bytes "
                     "[%0], [%1], %2, [%3];"
                     :: "r"(d1), "l"(s1), "r"((uint32_t)CHUNK_B), "r"(mb1) : "memory");
    }

    float4* O4 = reinterpret_cast<float4*>(out);

    #pragma unroll
    for (int c = 0; c < 2; c++) {
        mbar_wait_acq(c == 0 ? mb0 : mb1, 0);

        long gbase = (c == 0) ? base0 : base1;
        float4 a = buf[c][tid];
        float4 b = buf[c][tid + TPB];

        float acc = 0.0f;
        float4 ra, rb;
        ELEM(a.x, ra.x, acc);  ELEM(a.y, ra.y, acc);
        ELEM(a.z, ra.z, acc);  ELEM(a.w, ra.w, acc);
        ELEM(b.x, rb.x, acc);  ELEM(b.y, rb.y, acc);
        ELEM(b.z, rb.z, acc);  ELEM(b.w, rb.w, acc);

        if (acc >= 0.5f - EPS) {            // rare exact fixup
            FIX(a.x, ra.x);  FIX(a.y, ra.y);  FIX(a.z, ra.z);  FIX(a.w, ra.w);
            FIX(b.x, rb.x);  FIX(b.y, rb.y);  FIX(b.z, rb.z);  FIX(b.w, rb.w);
        }

        O4[gbase + tid]       = ra;
        O4[gbase + tid + TPB] = rb;
    }
}

// Generic fallback for shapes that don't fit exactly (perf irrelevant).
__global__ __launch_bounds__(TPB)
void logodds_generic_kernel(const float* __restrict__ Xs,
                            const float* __restrict__ bins,
                            float* __restrict__ out,
                            int n) {
    int i = blockIdx.x * blockDim.x + threadIdx.x;
    int stride = gridDim.x * blockDim.x;
    for (; i < n; i += stride) {
        float x  = Xs[i];
        float h  = fmaf(lg2a(x) - lg2a(1.0f - x), KU, 31.0f);
        float fu = rintf(h);
        float d  = h - fu;
        float v  = fminf(fmaxf(fmaf(fu, STEP, -6.0f), -6.0f), 6.0f);
        if (fabsf(d) >= 0.5f - EPS) v = slow_val(x, bins);
        out[i] = v;
    }
}

extern "C" void kernel_launch(void* const* d_in, const int* in_sizes, int n_in,
                              void* d_out, int out_size) {
    const float* Xs   = (const float*)d_in[0];
    const float* bins = (const float*)d_in[1];
    float* out        = (float*)d_out;
    int n = in_sizes[0];

    int per_blk = 2 * CHUNK_F4;               // float4s per block
    int n4 = n >> 2;

    if ((n & 3) == 0 && n4 > 0 && n4 % per_blk == 0 &&
        ((uintptr_t)Xs & 15) == 0 && ((uintptr_t)out & 15) == 0) {
        logodds_tma_kernel<<<n4 / per_blk, TPB>>>(Xs, bins, out);
    } else {
        int blocks = (n + TPB - 1) / TPB;
        if (blocks > 8192) blocks = 8192;
        if (blocks < 1) blocks = 1;
        logodds_generic_kernel<<<blocks, TPB>>>(Xs, bins, out, n);
    }
}